// round 4
// baseline (speedup 1.0000x reference)
#include <cuda_runtime.h>

// PatchIoULoss: reference's anchor loops run exactly once (B=16<64, C=1<64).
// Per batch b over the top-left 64x64 patch of (16,1,1024,1024) f32 images:
//   iand_b = sum(pred*target), ior_b = sum(pred)+sum(target)-iand_b
//   out = sum_b (1 - iand_b/ior_b)
//
// R3 post-mortem: 38 regs forced the 8 loads/thread into >=2 serialized
// round trips. R4: 1024 threads/block, exactly ONE float4 pair per thread
// (single memory round trip), 2-value reduction (I and S=sumP+sumT), and the
// R3 single-double-atomic finalize (count in integer part, payload/32 in
// fraction; the atomic return value identifies the last arriver).

#define BATCH 16
#define WIMG  1024
#define NT    1024

__device__ double g_acc = 0.0;

__global__ void __launch_bounds__(NT, 1)
patch_iou_kernel(const float* __restrict__ pred,
                 const float* __restrict__ target,
                 float* __restrict__ out)
{
    const int b   = blockIdx.x;
    const int tid = threadIdx.x;

    const float4* __restrict__ p =
        reinterpret_cast<const float4*>(pred   + (size_t)b * WIMG * WIMG);
    const float4* __restrict__ t =
        reinterpret_cast<const float4*>(target + (size_t)b * WIMG * WIMG);

    // Patch = 64 rows x 16 float4/row, row stride 256 float4.
    // 1024 threads -> exactly one float4 pair each. Both loads issue
    // back-to-back: one memory round trip.
    const int idx = ((tid >> 4) << 8) | (tid & 15);
    const float4 pv = p[idx];
    const float4 tv = t[idx];

    float iand = pv.x * tv.x;
    iand = fmaf(pv.y, tv.y, iand);
    iand = fmaf(pv.z, tv.z, iand);
    iand = fmaf(pv.w, tv.w, iand);
    float s = ((pv.x + pv.y) + (pv.z + pv.w)) +
              ((tv.x + tv.y) + (tv.z + tv.w));   // sumP + sumT combined

    // Level-1 warp reduction (2 independent shuffle chains).
#pragma unroll
    for (int o = 16; o > 0; o >>= 1) {
        iand += __shfl_down_sync(0xffffffffu, iand, o);
        s    += __shfl_down_sync(0xffffffffu, s,    o);
    }

    __shared__ float s_i[32], s_s[32];
    const int w = tid >> 5, l = tid & 31;
    if (l == 0) { s_i[w] = iand; s_s[w] = s; }
    __syncthreads();

    // Level-2: warp 0 reduces the 32 per-warp partials.
    if (w == 0) {
        float I = s_i[l];
        float S = s_s[l];
#pragma unroll
        for (int o = 16; o > 0; o >>= 1) {
            I += __shfl_down_sync(0xffffffffu, I, o);
            S += __shfl_down_sync(0xffffffffu, S, o);
        }
        if (l == 0) {
            const float loss = 1.0f - __fdividef(I, S - I);
            // loss in (0,1); sum of loss/32 over 16 blocks stays in (0,0.5),
            // so the integer part of g_acc is exactly the arrival count.
            const double term = (double)loss * (1.0 / 32.0) + 1.0;
            const double old  = atomicAdd(&g_acc, term);
            if (old > 14.75) {                    // 16th (last) arriver
                *out  = (float)((old + term - 16.0) * 32.0);
                g_acc = 0.0;                      // reset for next replay
            }
        }
    }
}

extern "C" void kernel_launch(void* const* d_in, const int* in_sizes, int n_in,
                              void* d_out, int out_size)
{
    const float* pred   = (const float*)d_in[0];
    const float* target = (const float*)d_in[1];
    float* out          = (float*)d_out;
    patch_iou_kernel<<<BATCH, NT>>>(pred, target, out);
}

// round 6
// speedup vs baseline: 1.0385x; 1.0385x over previous
#include <cuda_runtime.h>

// PatchIoULoss: reference's anchor loops run exactly once (B=16<64, C=1<64).
// Per batch b over the top-left 64x64 patch of (16,1,1024,1024) f32 images:
//   iand_b = sum(pred*target), ior_b = sum(pred)+sum(target)-iand_b
//   out = sum_b (1 - iand_b/ior_b)
//
// R5 post-mortem: redux.sync.add.f32 is not supported on sm_103 (ptxas
// reject). R6 = proven R4 structure: 16 blocks x 1024 threads, exactly one
// float4 pair per thread (single memory round trip, regs=18), two-level
// shuffle reduction of (I, S=sumP+sumT), and the single-double-atomic
// finalize (count in integer part, payload/32 in fraction; atomic return
// value identifies the last arriver -- no fence, no ticket, no re-read).

#define BATCH 16
#define WIMG  1024
#define NT    1024

__device__ double g_acc = 0.0;

__global__ void __launch_bounds__(NT, 1)
patch_iou_kernel(const float* __restrict__ pred,
                 const float* __restrict__ target,
                 float* __restrict__ out)
{
    const int b   = blockIdx.x;
    const int tid = threadIdx.x;

    const float4* __restrict__ p =
        reinterpret_cast<const float4*>(pred   + (size_t)b * WIMG * WIMG);
    const float4* __restrict__ t =
        reinterpret_cast<const float4*>(target + (size_t)b * WIMG * WIMG);

    // Patch = 64 rows x 16 float4/row, row stride 256 float4.
    // 1024 threads -> exactly one float4 pair each; both loads issue
    // back-to-back => a single memory round trip.
    const int idx = ((tid >> 4) << 8) | (tid & 15);
    const float4 pv = p[idx];
    const float4 tv = t[idx];

    float iand = pv.x * tv.x;
    iand = fmaf(pv.y, tv.y, iand);
    iand = fmaf(pv.z, tv.z, iand);
    iand = fmaf(pv.w, tv.w, iand);
    float s = ((pv.x + pv.y) + (pv.z + pv.w)) +
              ((tv.x + tv.y) + (tv.z + tv.w));   // sumP + sumT combined

    // Level-1: two independent shuffle chains (pipeline per round).
#pragma unroll
    for (int o = 16; o > 0; o >>= 1) {
        iand += __shfl_down_sync(0xffffffffu, iand, o);
        s    += __shfl_down_sync(0xffffffffu, s,    o);
    }

    __shared__ float s_i[32], s_s[32];
    const int w = tid >> 5, l = tid & 31;
    if (l == 0) { s_i[w] = iand; s_s[w] = s; }
    __syncthreads();

    // Level-2: warp 0 reduces the 32 per-warp partials.
    if (w == 0) {
        float I = s_i[l];
        float S = s_s[l];
#pragma unroll
        for (int o = 16; o > 0; o >>= 1) {
            I += __shfl_down_sync(0xffffffffu, I, o);
            S += __shfl_down_sync(0xffffffffu, S, o);
        }
        if (l == 0) {
            const float loss = 1.0f - __fdividef(I, S - I);
            // loss in (0,1); sum of loss/32 over 16 blocks stays in (0,0.5),
            // so the integer part of g_acc is exactly the arrival count and
            // the atomic return value identifies the last arriver.
            const double term = (double)loss * (1.0 / 32.0) + 1.0;
            const double old  = atomicAdd(&g_acc, term);
            if (old > 14.75) {                    // 16th (last) arriver
                *out  = (float)((old + term - 16.0) * 32.0);
                g_acc = 0.0;                      // reset for next replay
            }
        }
    }
}

extern "C" void kernel_launch(void* const* d_in, const int* in_sizes, int n_in,
                              void* d_out, int out_size)
{
    const float* pred   = (const float*)d_in[0];
    const float* target = (const float*)d_in[1];
    float* out          = (float*)d_out;
    patch_iou_kernel<<<BATCH, NT>>>(pred, target, out);
}

// round 7
// speedup vs baseline: 1.0435x; 1.0048x over previous
#include <cuda_runtime.h>

// PatchIoULoss: reference's anchor loops run exactly once (B=16<64, C=1<64).
// Per batch b over the top-left 64x64 patch of (16,1,1024,1024) f32 images:
//   iand_b = sum(pred*target), ior_b = sum(pred)+sum(target)-iand_b
//   out = sum_b (1 - iand_b/ior_b)
//
// R6 post-mortem: bench pinned at 6.656us (= R1) across kernels spanning
// 4.96-6.11us in ncu => harness replay floor + +-0.25us noise. R7 keeps the
// proven structure (16x1024, one float4 pair/thread = single memory round
// trip, regs 18, double-packed single-atomic finalize) and trims one shuffle
// round from the level-2 tail (lanes 0-15 pre-combine two partials each).

#define BATCH 16
#define WIMG  1024
#define NT    1024

__device__ double g_acc = 0.0;   // integer part = arrival count, fraction = sum(loss)/32

__global__ void __launch_bounds__(NT, 1)
patch_iou_kernel(const float* __restrict__ pred,
                 const float* __restrict__ target,
                 float* __restrict__ out)
{
    const int b   = blockIdx.x;
    const int tid = threadIdx.x;

    const float4* __restrict__ p =
        reinterpret_cast<const float4*>(pred   + (size_t)b * WIMG * WIMG);
    const float4* __restrict__ t =
        reinterpret_cast<const float4*>(target + (size_t)b * WIMG * WIMG);

    // Patch = 64 rows x 16 float4/row, row stride 256 float4.
    // 1024 threads -> exactly one float4 pair each; both loads issue
    // back-to-back => a single memory round trip.
    const int idx = ((tid >> 4) << 8) | (tid & 15);
    const float4 pv = p[idx];
    const float4 tv = t[idx];

    float iand = pv.x * tv.x;
    iand = fmaf(pv.y, tv.y, iand);
    iand = fmaf(pv.z, tv.z, iand);
    iand = fmaf(pv.w, tv.w, iand);
    float s = ((pv.x + pv.y) + (pv.z + pv.w)) +
              ((tv.x + tv.y) + (tv.z + tv.w));   // sumP + sumT combined

    // Level-1: two independent shuffle chains (pipeline per round).
#pragma unroll
    for (int o = 16; o > 0; o >>= 1) {
        iand += __shfl_down_sync(0xffffffffu, iand, o);
        s    += __shfl_down_sync(0xffffffffu, s,    o);
    }

    __shared__ float s_i[32], s_s[32];
    const int w = tid >> 5, l = tid & 31;
    if (l == 0) { s_i[w] = iand; s_s[w] = s; }
    __syncthreads();

    // Level-2: lanes 0-15 of warp 0 each combine two partials (replaces one
    // 26-cyc shuffle round with LDS+FADD), then 4 shuffle rounds.
    if (w == 0 && l < 16) {
        float I = s_i[l] + s_i[l + 16];
        float S = s_s[l] + s_s[l + 16];
#pragma unroll
        for (int o = 8; o > 0; o >>= 1) {
            I += __shfl_down_sync(0x0000ffffu, I, o);
            S += __shfl_down_sync(0x0000ffffu, S, o);
        }
        if (l == 0) {
            const float loss = 1.0f - __fdividef(I, S - I);
            // loss in (0,1); sum of loss/32 over 16 blocks stays in (0,0.5),
            // so the integer part of g_acc is exactly the arrival count and
            // the atomic return value identifies the last arriver.
            const double term = (double)loss * (1.0 / 32.0) + 1.0;
            const double old  = atomicAdd(&g_acc, term);
            if (old > 14.75) {                    // 16th (last) arriver
                *out  = (float)((old + term - 16.0) * 32.0);
                g_acc = 0.0;                      // reset for next replay
            }
        }
    }
}

extern "C" void kernel_launch(void* const* d_in, const int* in_sizes, int n_in,
                              void* d_out, int out_size)
{
    const float* pred   = (const float*)d_in[0];
    const float* target = (const float*)d_in[1];
    float* out          = (float*)d_out;
    patch_iou_kernel<<<BATCH, NT>>>(pred, target, out);
}